// round 1
// baseline (speedup 1.0000x reference)
#include <cuda_runtime.h>

#define N_WL   31
#define RADIUS 512
#define DIAM   1024
#define NPIX   (DIAM * DIAM)
#define NTOT   (NPIX * N_WL)     // 32,505,856

__global__ __launch_bounds__(256) void doe_kernel(
    const float* __restrict__ hmw,        // height_map_weight [512]
    const float* __restrict__ field_r,    // [NTOT]
    const float* __restrict__ field_i,    // [NTOT]
    const float* __restrict__ wavelength, // [31]
    const float* __restrict__ noise,      // [NPIX]
    const float* __restrict__ rad,        // [NPIX]
    const float* __restrict__ aper,       // [NPIX]
    float* __restrict__ out)              // [2*NTOT]
{
    __shared__ float s_coef[N_WL];
    __shared__ float s_table[RADIUS];
    const int t = threadIdx.x;

    // coef[wl] = (2*pi / wl) * (refractive_index(wl) - 1)   -- exact fp32 op order,
    // no contraction (phase magnitude ~1.6e4 rad makes this ulp-sensitive).
    if (t < N_WL) {
        float w  = wavelength[t];
        float dn = __fadd_rn(__fadd_rn(1.5f, __fdiv_rn(4e-15f, __fmul_rn(w, w))), -1.0f);
        float k  = __fdiv_rn(6.28318530717958647692f, w);
        s_coef[t] = __fmul_rn(k, dn);
    }
    {
        // q_base_height = lam0 / (n(lam0) - 1) in fp32
        const float lam0 = 7e-7f;
        float n0 = __fadd_rn(1.5f, __fdiv_rn(4e-15f, __fmul_rn(lam0, lam0)));
        float q  = __fdiv_rn(lam0, __fadd_rn(n0, -1.0f));
        for (int j = t; j < RADIUS; j += 256) {
            float w = fminf(fmaxf(hmw[j], -1.0f), 1.0f);
            float normed = __fmul_rn(__fadd_rn(w, 1.0f), 0.5f);
            s_table[j] = __fadd_rn(0.002f, -__fmul_rn(q, normed));  // no FMA contraction
        }
    }
    __syncthreads();

    const int gid = blockIdx.x * 256 + t;
    const int i   = gid * 4;            // NTOT divisible by 4; grid sized exactly
    // element i -> pixel p = i/31, wavelength w0 = i%31
    const int p  = i / N_WL;
    const int w0 = i - p * N_WL;
    const int split = N_WL - w0;        // elements of this 4-pack still in pixel p
    const bool two  = (split < 4);

    const float apA = aper[p];
    const float apB = two ? aper[p + 1] : apA;

    float4 o_r, o_i;
    if (apA == 0.0f && apB == 0.0f) {
        // outside aperture: reference multiplies by 0 -> exact zeros; skip loads + trig
        o_r = make_float4(0.f, 0.f, 0.f, 0.f);
        o_i = o_r;
    } else {
        // hmap for pixel A (and B if the pack straddles a pixel boundary)
        float rA  = rad[p];
        int   ixA = min(max((int)ceilf(rA) - 1, 0), RADIUS - 1);
        float hA  = __fadd_rn((rA <= (float)RADIUS) ? s_table[ixA] : 0.0f, noise[p]);
        float hB  = hA;
        if (two) {
            float rB  = rad[p + 1];
            int   ixB = min(max((int)ceilf(rB) - 1, 0), RADIUS - 1);
            hB = __fadd_rn((rB <= (float)RADIUS) ? s_table[ixB] : 0.0f, noise[p + 1]);
        }

        float4 fr4 = *reinterpret_cast<const float4*>(field_r + i);
        float4 fi4 = *reinterpret_cast<const float4*>(field_i + i);
        float frj[4] = {fr4.x, fr4.y, fr4.z, fr4.w};
        float fij[4] = {fi4.x, fi4.y, fi4.z, fi4.w};
        float orj[4], oij[4];

#pragma unroll
        for (int j = 0; j < 4; j++) {
            const bool  inB  = (j >= split);
            const float h    = inB ? hB : hA;
            const float a    = inB ? apB : apA;
            const int   widx = w0 + j - (inB ? N_WL : 0);
            const float phase = __fmul_rn(s_coef[widx], h);
            float s, c;
            sincosf(phase, &s, &c);            // accurate path; |phase| < 1.06e5
            orj[j] = (frj[j] * c - fij[j] * s) * a;
            oij[j] = (frj[j] * s + fij[j] * c) * a;
        }
        o_r = make_float4(orj[0], orj[1], orj[2], orj[3]);
        o_i = make_float4(oij[0], oij[1], oij[2], oij[3]);
    }

    *reinterpret_cast<float4*>(out + i)        = o_r;
    *reinterpret_cast<float4*>(out + NTOT + i) = o_i;
}

extern "C" void kernel_launch(void* const* d_in, const int* in_sizes, int n_in,
                              void* d_out, int out_size) {
    const float* hmw = (const float*)d_in[0];
    const float* fr  = (const float*)d_in[1];
    const float* fi  = (const float*)d_in[2];
    const float* wl  = (const float*)d_in[3];
    const float* nz  = (const float*)d_in[4];
    const float* rd  = (const float*)d_in[5];
    const float* ap  = (const float*)d_in[6];

    const int threads = 256;
    const int blocks  = (NTOT / 4) / threads;   // 8,126,464 / 256 = 31,744 exact
    doe_kernel<<<blocks, threads>>>(hmw, fr, fi, wl, nz, rd, ap, (float*)d_out);
}

// round 3
// speedup vs baseline: 1.1350x; 1.1350x over previous
#include <cuda_runtime.h>

#define N_WL   31
#define RADIUS 512
#define DIAM   1024
#define NPIX   (DIAM * DIAM)
#define NTOT   (NPIX * N_WL)     // 32,505,856 = 31 * 2^20, divisible by 8

__global__ __launch_bounds__(256) void doe_kernel(
    const float* __restrict__ hmw,        // height_map_weight [512]
    const float* __restrict__ field_r,    // [NTOT]
    const float* __restrict__ field_i,    // [NTOT]
    const float* __restrict__ wavelength, // [31]
    const float* __restrict__ noise,      // [NPIX]
    const float* __restrict__ rad,        // [NPIX]
    const float* __restrict__ aper,       // [NPIX]
    float* __restrict__ out)              // [2*NTOT]
{
    __shared__ float s_coef[N_WL];
    __shared__ float s_table[RADIUS];
    const int t = threadIdx.x;

    // coef[wl] = (2*pi / wl) * (n(wl) - 1) -- exact fp32 op order, no contraction
    // (phase ~1.6e4 rad; 1-ulp drift in the chain shifts cos by ~1e-3).
    if (t < N_WL) {
        float w  = wavelength[t];
        float dn = __fadd_rn(__fadd_rn(1.5f, __fdiv_rn(4e-15f, __fmul_rn(w, w))), -1.0f);
        float k  = __fdiv_rn(6.28318530717958647692f, w);
        s_coef[t] = __fmul_rn(k, dn);
    }
    {
        const float lam0 = 7e-7f;
        float n0 = __fadd_rn(1.5f, __fdiv_rn(4e-15f, __fmul_rn(lam0, lam0)));
        float q  = __fdiv_rn(lam0, __fadd_rn(n0, -1.0f));
        for (int j = t; j < RADIUS; j += 256) {
            float w = fminf(fmaxf(hmw[j], -1.0f), 1.0f);
            float normed = __fmul_rn(__fadd_rn(w, 1.0f), 0.5f);
            s_table[j] = __fadd_rn(0.002f, -__fmul_rn(q, normed));
        }
    }
    __syncthreads();

    const int gid = blockIdx.x * 256 + t;
    const int i   = gid * 8;            // exact grid, no tail
    const int p   = i / N_WL;
    const int w0  = i - p * N_WL;
    const int split = N_WL - w0;        // elems of this 8-pack still in pixel p
    const bool two  = (split < 8);      // pack straddles one pixel boundary

    // Per-pixel scalars first (tiny arrays, L2-resident) so they overlap with
    // other warps' field traffic.
    const float apA = aper[p];
    const float apB = two ? aper[p + 1] : apA;

    if (apA == 0.0f && apB == 0.0f) {
        // Outside aperture: reference multiplies by 0 -> exact zeros.
        const float4 z = make_float4(0.f, 0.f, 0.f, 0.f);
        __stcs(reinterpret_cast<float4*>(out + i),            z);
        __stcs(reinterpret_cast<float4*>(out + i + 4),        z);
        __stcs(reinterpret_cast<float4*>(out + NTOT + i),     z);
        __stcs(reinterpret_cast<float4*>(out + NTOT + i + 4), z);
        return;
    }

    float rA  = rad[p];
    int   ixA = min(max((int)ceilf(rA) - 1, 0), RADIUS - 1);
    float hA  = __fadd_rn((rA <= (float)RADIUS) ? s_table[ixA] : 0.0f, noise[p]);
    float hB  = hA;
    if (two) {
        float rB  = rad[p + 1];
        int   ixB = min(max((int)ceilf(rB) - 1, 0), RADIUS - 1);
        hB = __fadd_rn((rB <= (float)RADIUS) ? s_table[ixB] : 0.0f, noise[p + 1]);
    }

    // Issue all 4 field loads back-to-back (MLP=4 x 16B), streaming policy.
    float4 fr0 = __ldcs(reinterpret_cast<const float4*>(field_r + i));
    float4 fr1 = __ldcs(reinterpret_cast<const float4*>(field_r + i + 4));
    float4 fi0 = __ldcs(reinterpret_cast<const float4*>(field_i + i));
    float4 fi1 = __ldcs(reinterpret_cast<const float4*>(field_i + i + 4));

    float frj[8] = {fr0.x, fr0.y, fr0.z, fr0.w, fr1.x, fr1.y, fr1.z, fr1.w};
    float fij[8] = {fi0.x, fi0.y, fi0.z, fi0.w, fi1.x, fi1.y, fi1.z, fi1.w};
    float orj[8], oij[8];

#pragma unroll
    for (int j = 0; j < 8; j++) {
        const bool  inB  = (j >= split);
        const float h    = inB ? hB : hA;
        const float a    = inB ? apB : apA;
        const int   widx = w0 + j - (inB ? N_WL : 0);
        const float phase = __fmul_rn(s_coef[widx], h);
        float s, c;
        sincosf(phase, &s, &c);            // accurate path; |phase| < 1.06e5
        orj[j] = (frj[j] * c - fij[j] * s) * a;
        oij[j] = (frj[j] * s + fij[j] * c) * a;
    }

    __stcs(reinterpret_cast<float4*>(out + i),
           make_float4(orj[0], orj[1], orj[2], orj[3]));
    __stcs(reinterpret_cast<float4*>(out + i + 4),
           make_float4(orj[4], orj[5], orj[6], orj[7]));
    __stcs(reinterpret_cast<float4*>(out + NTOT + i),
           make_float4(oij[0], oij[1], oij[2], oij[3]));
    __stcs(reinterpret_cast<float4*>(out + NTOT + i + 4),
           make_float4(oij[4], oij[5], oij[6], oij[7]));
}

extern "C" void kernel_launch(void* const* d_in, const int* in_sizes, int n_in,
                              void* d_out, int out_size) {
    const float* hmw = (const float*)d_in[0];
    const float* fr  = (const float*)d_in[1];
    const float* fi  = (const float*)d_in[2];
    const float* wl  = (const float*)d_in[3];
    const float* nz  = (const float*)d_in[4];
    const float* rd  = (const float*)d_in[5];
    const float* ap  = (const float*)d_in[6];

    const int threads = 256;
    const int blocks  = (NTOT / 8) / threads;   // 4,063,232 / 256 = 15,872 exact
    doe_kernel<<<blocks, threads>>>(hmw, fr, fi, wl, nz, rd, ap, (float*)d_out);
}